// round 3
// baseline (speedup 1.0000x reference)
#include <cuda_runtime.h>
#include <stdint.h>

#define BB 16
#define NN 4096
#define DD 32
#define CC 64
#define KK 16
#define KP 17          // k+1, includes self
#define TS 128         // candidate tile size
#define TST 132        // padded smem row stride (floats), 16B-aligned rows
#define NTILES (NN / TS)
#define THREADS 128
#define WARPS (THREADS / 32)
#define QPB THREADS    // queries per block (1 per lane, 32 per warp)

typedef unsigned long long u64;

__device__ __forceinline__ u64 pk2(float a, float b) {
    u64 r; asm("mov.b64 %0, {%1,%2};" : "=l"(r) : "f"(a), "f"(b)); return r;
}
__device__ __forceinline__ u64 fma2(u64 a, u64 b, u64 c) {
    u64 d; asm("fma.rn.f32x2 %0, %1, %2, %3;" : "=l"(d) : "l"(a), "l"(b), "l"(c));
    return d;
}
__device__ __forceinline__ void up2(u64 v, float& a, float& b) {
    asm("mov.b64 {%0,%1}, %2;" : "=f"(a), "=f"(b) : "l"(v));
}

// Balanced binary tree sum with XLA warp-shfl grouping:
// level1 pairs stride 16, then 8, 4, 2, 1. Matches
// EmitFullWarpShuffleDownLoopForReduce over 32 lanes (1 elem/lane).
__device__ __forceinline__ float tree32(float t[32]) {
    #pragma unroll
    for (int off = 16; off >= 1; off >>= 1)
        #pragma unroll
        for (int i = 0; i < off; ++i)
            t[i] = __fadd_rn(t[i], t[i + off]);
    return t[0];
}

__global__ __launch_bounds__(THREADS, 4)
void knn_select_kernel(const float* __restrict__ points,
                       const float* __restrict__ features,
                       float* __restrict__ out)
{
    __shared__ float s_t[DD][TST];        // transposed candidate tile [dim][cand]
    __shared__ float s_rc[TS];            // candidate squared norms
    __shared__ int   s_idx[WARPS][32][KK];// per-query neighbor lists

    const int lane = threadIdx.x & 31;
    const int warp = threadIdx.x >> 5;
    const int b    = blockIdx.x >> 5;            // 32 CTAs per batch
    const int q0b  = (blockIdx.x & 31) * QPB;    // first query of this CTA
    const int nq   = q0b + warp * 32 + lane;     // this lane's query

    const float* pb = points   + (size_t)b * NN * DD;
    const float* fb = features + (size_t)b * NN * CC;

    // ---- query point into registers, duplicated into f32x2 pairs ----
    // rq = tree32 over rounded squares (XLA row-reduce order).
    u64 qd[DD];
    float rq;
    {
        float x[DD];
        const float4* qp = (const float4*)(pb + (size_t)nq * DD);
        #pragma unroll
        for (int j4 = 0; j4 < DD / 4; ++j4) {
            float4 v = __ldg(qp + j4);
            qd[j4*4+0] = pk2(v.x, v.x);
            qd[j4*4+1] = pk2(v.y, v.y);
            qd[j4*4+2] = pk2(v.z, v.z);
            qd[j4*4+3] = pk2(v.w, v.w);
            x[j4*4+0] = __fmul_rn(v.x, v.x);
            x[j4*4+1] = __fmul_rn(v.y, v.y);
            x[j4*4+2] = __fmul_rn(v.z, v.z);
            x[j4*4+3] = __fmul_rn(v.w, v.w);
        }
        rq = tree32(x);
    }

    // ---- per-lane running top-17 (unsorted + tracked worst) ----
    float td[KP]; int ti[KP];
    #pragma unroll
    for (int i = 0; i < KP; ++i) { td[i] = __int_as_float(0x7f800000); ti[i] = 0x7fffffff; }
    float wd = __int_as_float(0x7f800000); int wi = 0x7fffffff; int wp = 0;

    auto ins = [&](float dv, int iv) {
        if (dv < wd || (dv == wd && iv < wi)) {
            td[wp] = dv; ti[wp] = iv;
            wd = td[0]; wi = ti[0]; wp = 0;
            #pragma unroll
            for (int s = 1; s < KP; ++s)
                if (td[s] > wd || (td[s] == wd && ti[s] > wi)) { wd = td[s]; wi = ti[s]; wp = s; }
        }
    };

    for (int tile = 0; tile < NTILES; ++tile) {
        __syncthreads();
        // load candidate tile transposed: [dim][cand]
        {
            const float4* src = (const float4*)(pb + (size_t)tile * TS * DD);
            #pragma unroll
            for (int it = 0; it < (TS * DD / 4) / THREADS; ++it) {
                int v  = threadIdx.x + it * THREADS;
                int c  = v >> 3;
                int j0 = (v & 7) << 2;
                float4 p4 = __ldg(src + v);
                s_t[j0+0][c] = p4.x;
                s_t[j0+1][c] = p4.y;
                s_t[j0+2][c] = p4.z;
                s_t[j0+3][c] = p4.w;
            }
        }
        __syncthreads();
        // candidate norms: tree32 over rounded squares (matches reference r)
        {
            int c = threadIdx.x;   // THREADS == TS
            float x[DD];
            #pragma unroll
            for (int j = 0; j < DD; ++j) {
                float v = s_t[j][c];
                x[j] = __fmul_rn(v, v);
            }
            s_rc[c] = tree32(x);
        }
        __syncthreads();

        // distances: uniform-address (broadcast) LDS.128 + packed FFMA2.
        // m = sequential ascending-k fp32 FMA chain from 0 (cublas sgemm order).
        #pragma unroll 1
        for (int c4 = 0; c4 < TS; c4 += 4) {
            u64 a01 = 0ull, a23 = 0ull;
            #pragma unroll
            for (int j = 0; j < DD; ++j) {
                ulonglong2 p2 = *(const ulonglong2*)&s_t[j][c4];
                a01 = fma2(qd[j], p2.x, a01);
                a23 = fma2(qd[j], p2.y, a23);
            }
            float m0, m1, m2, m3;
            up2(a01, m0, m1); up2(a23, m2, m3);
            int gi = tile * TS + c4;
            float d0 = __fadd_rn(__fsub_rn(rq, 2.f * m0), s_rc[c4+0]);
            float d1 = __fadd_rn(__fsub_rn(rq, 2.f * m1), s_rc[c4+1]);
            float d2 = __fadd_rn(__fsub_rn(rq, 2.f * m2), s_rc[c4+2]);
            float d3 = __fadd_rn(__fsub_rn(rq, 2.f * m3), s_rc[c4+3]);
            ins(d0, gi + 0);
            ins(d1, gi + 1);
            ins(d2, gi + 2);
            ins(d3, gi + 3);
        }
    }

    // ---- sort my 17 ascending by (dist, idx): matches jax top_k(-D) stability ----
    for (int i = 1; i < KP; ++i) {
        float dv = td[i]; int iv = ti[i];
        int j = i - 1;
        while (j >= 0 && (td[j] > dv || (td[j] == dv && ti[j] > iv))) {
            td[j+1] = td[j]; ti[j+1] = ti[j]; --j;
        }
        td[j+1] = dv; ti[j+1] = iv;
    }
    // drop entry 0 (self), publish 16 neighbor indices
    #pragma unroll
    for (int kk = 0; kk < KK; ++kk) s_idx[warp][lane][kk] = ti[kk + 1];
    __syncwarp();

    // ---- gather + write: warp iterates its 32 queries, lanes split channels ----
    for (int qq = 0; qq < 32; ++qq) {
        int n = q0b + warp * 32 + qq;
        float c0 = fb[(size_t)n * CC + lane];
        float c1 = fb[(size_t)n * CC + lane + 32];
        float* ob = out + (size_t)(b * NN + n) * KK * (2 * CC);
        #pragma unroll
        for (int kk = 0; kk < KK; ++kk) {
            int nbv = s_idx[warp][qq][kk];
            const float* fr = fb + (size_t)nbv * CC;
            float g0 = __ldg(fr + lane);
            float g1 = __ldg(fr + lane + 32);
            float* orow = ob + kk * (2 * CC);
            orow[lane]      = g0;
            orow[32 + lane] = g1;
            orow[64 + lane] = g0 - c0;
            orow[96 + lane] = g1 - c1;
        }
    }
}

extern "C" void kernel_launch(void* const* d_in, const int* in_sizes, int n_in,
                              void* d_out, int out_size) {
    const float* points   = (const float*)d_in[0];
    const float* features = (const float*)d_in[1];
    float* out = (float*)d_out;
    (void)in_sizes; (void)n_in; (void)out_size;
    knn_select_kernel<<<BB * (NN / QPB), THREADS>>>(points, features, out);
}

// round 4
// speedup vs baseline: 1.5896x; 1.5896x over previous
#include <cuda_runtime.h>
#include <stdint.h>

#define BB 16
#define NN 4096
#define DD 32
#define CC 64
#define KK 16          // top-16 non-self neighbors, kept sorted ascending
#define TS 128         // candidate tile size
#define TST 132        // padded smem row stride (floats); 132*4=528B, 16B-aligned rows
#define NTILES (NN / TS)
#define THREADS 128
#define WARPS (THREADS / 32)

typedef unsigned long long u64;
typedef unsigned int u32;

__device__ __forceinline__ u64 pk2(float a, float b) {
    u64 r; asm("mov.b64 %0, {%1,%2};" : "=l"(r) : "f"(a), "f"(b)); return r;
}
__device__ __forceinline__ u64 fma2(u64 a, u64 b, u64 c) {
    u64 d; asm("fma.rn.f32x2 %0, %1, %2, %3;" : "=l"(d) : "l"(a), "l"(b), "l"(c));
    return d;
}
__device__ __forceinline__ void up2(u64 v, float& a, float& b) {
    asm("mov.b64 {%0,%1}, %2;" : "=f"(a), "=f"(b) : "l"(v));
}

// Balanced binary tree sum, XLA warp-shfl grouping (stride 16,8,4,2,1).
__device__ __forceinline__ float tree32(float t[32]) {
    #pragma unroll
    for (int off = 16; off >= 1; off >>= 1)
        #pragma unroll
        for (int i = 0; i < off; ++i)
            t[i] = __fadd_rn(t[i], t[i + off]);
    return t[0];
}

// Branch-free insert into ascending sorted k[0..15]; inserting UINT64_MAX is a no-op.
__device__ __forceinline__ void ins16(u64 k[KK], u64 nk) {
    #pragma unroll
    for (int s = KK - 1; s >= 1; --s) {
        u64 mn = (nk < k[s]) ? nk : k[s];
        k[s] = (k[s-1] > mn) ? k[s-1] : mn;
    }
    k[0] = (nk < k[0]) ? nk : k[0];
}

__global__ __launch_bounds__(THREADS, 4)
void knn_select_kernel(const float* __restrict__ points,
                       const float* __restrict__ features,
                       float* __restrict__ out)
{
    __shared__ float s_rc[NN];            // all candidate squared norms (tree32 order)
    __shared__ float s_t[DD][TST];        // transposed candidate tile [dim][cand]
    __shared__ int   s_idx[WARPS][32][KK];

    const int lane = threadIdx.x & 31;
    const int warp = threadIdx.x >> 5;
    const int b    = blockIdx.x >> 5;            // 32 CTAs per batch
    const int q0b  = (blockIdx.x & 31) * THREADS;
    const int nq   = q0b + warp * 32 + lane;     // this lane's query

    const float* pb = points   + (size_t)b * NN * DD;
    const float* fb = features + (size_t)b * NN * CC;

    // ---- precompute ALL candidate norms once (tree32, matches reference r) ----
    for (int c = threadIdx.x; c < NN; c += THREADS) {
        float x[DD];
        const float4* cp = (const float4*)(pb + (size_t)c * DD);
        #pragma unroll
        for (int j4 = 0; j4 < DD / 4; ++j4) {
            float4 v = __ldg(cp + j4);
            x[j4*4+0] = __fmul_rn(v.x, v.x);
            x[j4*4+1] = __fmul_rn(v.y, v.y);
            x[j4*4+2] = __fmul_rn(v.z, v.z);
            x[j4*4+3] = __fmul_rn(v.w, v.w);
        }
        s_rc[c] = tree32(x);
    }

    // ---- query point into scalar registers + rq (tree32) ----
    float qs[DD];
    float rq;
    {
        float x[DD];
        const float4* qp = (const float4*)(pb + (size_t)nq * DD);
        #pragma unroll
        for (int j4 = 0; j4 < DD / 4; ++j4) {
            float4 v = __ldg(qp + j4);
            qs[j4*4+0] = v.x; qs[j4*4+1] = v.y; qs[j4*4+2] = v.z; qs[j4*4+3] = v.w;
            x[j4*4+0] = __fmul_rn(v.x, v.x);
            x[j4*4+1] = __fmul_rn(v.y, v.y);
            x[j4*4+2] = __fmul_rn(v.z, v.z);
            x[j4*4+3] = __fmul_rn(v.w, v.w);
        }
        rq = tree32(x);
    }

    // ---- selection state: sorted top-16 keys + 4-deep lane buffer ----
    u64 k[KK];
    #pragma unroll
    for (int i = 0; i < KK; ++i) k[i] = ~0ull;
    u64 b0 = ~0ull, b1 = ~0ull, b2 = ~0ull, b3 = ~0ull;
    u64 wk = ~0ull;          // threshold = k[15] (refreshed at flushes)
    int count = 0;           // buffered entries

    const unsigned FULL = 0xffffffffu;

    for (int tile = 0; tile < NTILES; ++tile) {
        __syncthreads();
        // load candidate tile transposed: [dim][cand]
        {
            const float4* src = (const float4*)(pb + (size_t)tile * TS * DD);
            #pragma unroll
            for (int it = 0; it < (TS * DD / 4) / THREADS; ++it) {
                int v  = threadIdx.x + it * THREADS;
                int c  = v >> 3;
                int j0 = (v & 7) << 2;
                float4 p4 = __ldg(src + v);
                s_t[j0+0][c] = p4.x;
                s_t[j0+1][c] = p4.y;
                s_t[j0+2][c] = p4.z;
                s_t[j0+3][c] = p4.w;
            }
        }
        __syncthreads();

        #pragma unroll 1
        for (int c8 = 0; c8 < TS; c8 += 8) {
            // ---- 8 candidates, 4 independent packed FMA chains ----
            u64 a01 = 0ull, a23 = 0ull, a45 = 0ull, a67 = 0ull;
            #pragma unroll
            for (int j = 0; j < DD; ++j) {
                u64 qj = pk2(qs[j], qs[j]);
                ulonglong2 pA = *(const ulonglong2*)&s_t[j][c8];
                ulonglong2 pB = *(const ulonglong2*)&s_t[j][c8 + 4];
                a01 = fma2(qj, pA.x, a01);
                a23 = fma2(qj, pA.y, a23);
                a45 = fma2(qj, pB.x, a45);
                a67 = fma2(qj, pB.y, a67);
            }
            float m[8];
            up2(a01, m[0], m[1]); up2(a23, m[2], m[3]);
            up2(a45, m[4], m[5]); up2(a67, m[6], m[7]);

            const int gi = tile * TS + c8;
            float4 rcA = *(const float4*)&s_rc[gi];
            float4 rcB = *(const float4*)&s_rc[gi + 4];
            float rc[8] = {rcA.x, rcA.y, rcA.z, rcA.w, rcB.x, rcB.y, rcB.z, rcB.w};

            u64 key[8];
            bool ps[8];
            int cnt = 0;
            #pragma unroll
            for (int t = 0; t < 8; ++t) {
                // D = fl(fl(rq - 2m) + rc)  — exact reference composition
                float d = __fadd_rn(__fsub_rn(rq, __fmul_rn(2.f, m[t])), rc[t]);
                int ci = gi + t;
                // d > 0 for all non-self candidates -> bit pattern | signbit is order-monotonic
                u32 mk = __float_as_uint(d) | 0x80000000u;
                u64 kv = ((u64)mk << 32) | (u32)ci;
                kv = (ci == nq) ? ~0ull : kv;     // exclude self by identity
                key[t] = kv;
                ps[t] = kv < wk;
                cnt += ps[t] ? 1 : 0;
            }

            if (__any_sync(FULL, count + cnt > 4)) {
                // flush buffers (converged, branch-free inserts; UMAX = no-op)
                ins16(k, b0); ins16(k, b1); ins16(k, b2); ins16(k, b3);
                b0 = b1 = b2 = b3 = ~0ull;
                count = 0;
                wk = k[KK-1];
            }
            if (__any_sync(FULL, cnt > 4)) {
                // rare (early tiles): direct insert all 8, predicated by sentinel
                #pragma unroll
                for (int t = 0; t < 8; ++t)
                    ins16(k, ps[t] ? key[t] : ~0ull);
                wk = k[KK-1];
            } else if (__any_sync(FULL, cnt > 0)) {
                // push passing keys into 4-deep shift buffer (SEL-only arm)
                #pragma unroll
                for (int t = 0; t < 8; ++t) {
                    b3 = ps[t] ? b2 : b3;
                    b2 = ps[t] ? b1 : b2;
                    b1 = ps[t] ? b0 : b1;
                    b0 = ps[t] ? key[t] : b0;
                }
                count += cnt;
            }
        }
    }

    // final flush
    ins16(k, b0); ins16(k, b1); ins16(k, b2); ins16(k, b3);

    // k[0..15] sorted ascending by (dist, idx) = reference neighbor order
    #pragma unroll
    for (int kk = 0; kk < KK; ++kk) s_idx[warp][lane][kk] = (int)(u32)k[kk];
    __syncwarp();

    // ---- gather + write: warp iterates its 32 queries, lanes split channels ----
    for (int qq = 0; qq < 32; ++qq) {
        int n = q0b + warp * 32 + qq;
        float c0 = fb[(size_t)n * CC + lane];
        float c1 = fb[(size_t)n * CC + lane + 32];
        float* ob = out + (size_t)(b * NN + n) * KK * (2 * CC);
        #pragma unroll
        for (int kk = 0; kk < KK; ++kk) {
            int nbv = s_idx[warp][qq][kk];
            const float* fr = fb + (size_t)nbv * CC;
            float g0 = __ldg(fr + lane);
            float g1 = __ldg(fr + lane + 32);
            float* orow = ob + kk * (2 * CC);
            __stcs(orow + lane,      g0);
            __stcs(orow + 32 + lane, g1);
            __stcs(orow + 64 + lane, g0 - c0);
            __stcs(orow + 96 + lane, g1 - c1);
        }
    }
}

extern "C" void kernel_launch(void* const* d_in, const int* in_sizes, int n_in,
                              void* d_out, int out_size) {
    const float* points   = (const float*)d_in[0];
    const float* features = (const float*)d_in[1];
    float* out = (float*)d_out;
    (void)in_sizes; (void)n_in; (void)out_size;
    knn_select_kernel<<<BB * (NN / THREADS), THREADS>>>(points, features, out);
}

// round 5
// speedup vs baseline: 1.7330x; 1.0902x over previous
#include <cuda_runtime.h>
#include <stdint.h>

#define BB 16
#define NN 4096
#define DD 32
#define CC 64
#define KK 16          // top-16 non-self neighbors, kept sorted ascending
#define TS 256         // candidate tile size
#define TST 260        // padded smem row stride (floats): 1040B, 16B-aligned, bank-rotated
#define NTILES (NN / TS)
#define THREADS 128
#define WARPS (THREADS / 32)

typedef unsigned long long u64;
typedef unsigned int u32;

__device__ float g_norms[BB * NN];   // precomputed candidate squared norms

__device__ __forceinline__ u64 pk2(float a, float b) {
    u64 r; asm("mov.b64 %0, {%1,%2};" : "=l"(r) : "f"(a), "f"(b)); return r;
}
__device__ __forceinline__ u64 fma2(u64 a, u64 b, u64 c) {
    u64 d; asm("fma.rn.f32x2 %0, %1, %2, %3;" : "=l"(d) : "l"(a), "l"(b), "l"(c));
    return d;
}
__device__ __forceinline__ void up2(u64 v, float& a, float& b) {
    asm("mov.b64 {%0,%1}, %2;" : "=f"(a), "=f"(b) : "l"(v));
}

// Balanced binary tree sum, XLA warp-shfl grouping (stride 16,8,4,2,1).
__device__ __forceinline__ float tree32(float t[32]) {
    #pragma unroll
    for (int off = 16; off >= 1; off >>= 1)
        #pragma unroll
        for (int i = 0; i < off; ++i)
            t[i] = __fadd_rn(t[i], t[i + off]);
    return t[0];
}

// Branch-free insert into ascending sorted k[0..15]; inserting UINT64_MAX is a no-op.
__device__ __forceinline__ void ins16(u64 k[KK], u64 nk) {
    #pragma unroll
    for (int s = KK - 1; s >= 1; --s) {
        u64 mn = (nk < k[s]) ? nk : k[s];
        k[s] = (k[s-1] > mn) ? k[s-1] : mn;
    }
    k[0] = (nk < k[0]) ? nk : k[0];
}

// threshold distance (float) from the worst kept key; sentinel -> +inf
__device__ __forceinline__ float thr_of(u64 wk) {
    u32 hi = (u32)(wk >> 32) ^ 0x80000000u;
    hi = hi < 0x7f800000u ? hi : 0x7f800000u;
    return __uint_as_float(hi);
}

__global__ void norms_kernel(const float* __restrict__ points) {
    int idx = blockIdx.x * blockDim.x + threadIdx.x;   // one row per thread
    if (idx >= BB * NN) return;
    const float4* cp = (const float4*)(points + (size_t)idx * DD);
    float x[DD];
    #pragma unroll
    for (int j4 = 0; j4 < DD / 4; ++j4) {
        float4 v = __ldg(cp + j4);
        x[j4*4+0] = __fmul_rn(v.x, v.x);
        x[j4*4+1] = __fmul_rn(v.y, v.y);
        x[j4*4+2] = __fmul_rn(v.z, v.z);
        x[j4*4+3] = __fmul_rn(v.w, v.w);
    }
    g_norms[idx] = tree32(x);
}

__global__ __launch_bounds__(THREADS, 4)
void knn_select_kernel(const float* __restrict__ points,
                       const float* __restrict__ features,
                       float* __restrict__ out)
{
    __shared__ float s_t[DD][TST];        // transposed candidate tile [dim][cand]
    __shared__ float s_rc[TS];            // candidate norms for this tile
    __shared__ int   s_idx[WARPS][32][KK];

    const int lane = threadIdx.x & 31;
    const int warp = threadIdx.x >> 5;
    const int b    = blockIdx.x >> 5;            // 32 CTAs per batch
    const int q0b  = (blockIdx.x & 31) * THREADS;
    const int nq   = q0b + warp * 32 + lane;     // this lane's query

    const float* pb = points   + (size_t)b * NN * DD;
    const float* fb = features + (size_t)b * NN * CC;

    // ---- query point into scalar registers + rq (tree32, reference order) ----
    float qs[DD];
    float rq;
    {
        float x[DD];
        const float4* qp = (const float4*)(pb + (size_t)nq * DD);
        #pragma unroll
        for (int j4 = 0; j4 < DD / 4; ++j4) {
            float4 v = __ldg(qp + j4);
            qs[j4*4+0] = v.x; qs[j4*4+1] = v.y; qs[j4*4+2] = v.z; qs[j4*4+3] = v.w;
            x[j4*4+0] = __fmul_rn(v.x, v.x);
            x[j4*4+1] = __fmul_rn(v.y, v.y);
            x[j4*4+2] = __fmul_rn(v.z, v.z);
            x[j4*4+3] = __fmul_rn(v.w, v.w);
        }
        rq = tree32(x);
    }

    // ---- selection state: sorted top-16 keys + 4-deep lane buffer ----
    u64 k[KK];
    #pragma unroll
    for (int i = 0; i < KK; ++i) k[i] = ~0ull;
    u64 b0 = ~0ull, b1 = ~0ull, b2 = ~0ull, b3 = ~0ull;
    float wdf = __int_as_float(0x7f800000);  // +inf
    int count = 0;

    const unsigned FULL = 0xffffffffu;

    for (int tile = 0; tile < NTILES; ++tile) {
        __syncthreads();
        // load candidate tile transposed: [dim][cand]
        {
            const float4* src = (const float4*)(pb + (size_t)tile * TS * DD);
            #pragma unroll
            for (int it = 0; it < (TS * DD / 4) / THREADS; ++it) {
                int v  = threadIdx.x + it * THREADS;
                int c  = v >> 3;
                int j0 = (v & 7) << 2;
                float4 p4 = src[v];
                s_t[j0+0][c] = p4.x;
                s_t[j0+1][c] = p4.y;
                s_t[j0+2][c] = p4.z;
                s_t[j0+3][c] = p4.w;
            }
            // tile candidate norms from precomputed global
            if (threadIdx.x < TS / 4) {
                float4 n4 = *(const float4*)&g_norms[b * NN + tile * TS + threadIdx.x * 4];
                *(float4*)&s_rc[threadIdx.x * 4] = n4;
            }
        }
        __syncthreads();

        #pragma unroll 1
        for (int c8 = 0; c8 < TS; c8 += 8) {
            // ---- 8 candidates, 4 independent packed FMA chains (ascending j) ----
            u64 a01 = 0ull, a23 = 0ull, a45 = 0ull, a67 = 0ull;
            #pragma unroll
            for (int j = 0; j < DD; ++j) {
                u64 qj = pk2(qs[j], qs[j]);
                ulonglong2 pA = *(const ulonglong2*)&s_t[j][c8];
                ulonglong2 pB = *(const ulonglong2*)&s_t[j][c8 + 4];
                a01 = fma2(qj, pA.x, a01);
                a23 = fma2(qj, pA.y, a23);
                a45 = fma2(qj, pB.x, a45);
                a67 = fma2(qj, pB.y, a67);
            }
            float m[8];
            up2(a01, m[0], m[1]); up2(a23, m[2], m[3]);
            up2(a45, m[4], m[5]); up2(a67, m[6], m[7]);

            const int gi = tile * TS + c8;
            float4 rcA = *(const float4*)&s_rc[c8];
            float4 rcB = *(const float4*)&s_rc[c8 + 4];
            float rc[8] = {rcA.x, rcA.y, rcA.z, rcA.w, rcB.x, rcB.y, rcB.z, rcB.w};

            // D = fl(fl(rq - 2m) + rc); FFMA(-2,m,rq) == FSUB(rq, FMUL(2,m)) bitwise
            float d[8];
            bool ps[8];
            int cnt = 0;
            #pragma unroll
            for (int t = 0; t < 8; ++t) {
                d[t] = __fadd_rn(__fmaf_rn(-2.f, m[t], rq), rc[t]);
                ps[t] = (d[t] <= wdf);          // cheap float gate (ties conservative)
                cnt += ps[t] ? 1 : 0;
            }

            if (__any_sync(FULL, cnt > 0)) {
                // pack exact keys only when somebody passed
                u64 key[8];
                #pragma unroll
                for (int t = 0; t < 8; ++t) {
                    int ci = gi + t;
                    u32 mk = __float_as_uint(d[t]) | 0x80000000u;
                    u64 kv = ((u64)mk << 32) | (u32)ci;
                    key[t] = (ci == nq) ? ~0ull : kv;   // exclude self by identity
                }

                if (__any_sync(FULL, count + cnt > 4)) {
                    ins16(k, b0); ins16(k, b1); ins16(k, b2); ins16(k, b3);
                    b0 = b1 = b2 = b3 = ~0ull;
                    count = 0;
                    wdf = thr_of(k[KK-1]);
                }
                if (__any_sync(FULL, cnt > 4)) {
                    #pragma unroll
                    for (int t = 0; t < 8; ++t)
                        ins16(k, ps[t] ? key[t] : ~0ull);
                    wdf = thr_of(k[KK-1]);
                } else {
                    #pragma unroll
                    for (int t = 0; t < 8; ++t) {
                        b3 = ps[t] ? b2 : b3;
                        b2 = ps[t] ? b1 : b2;
                        b1 = ps[t] ? b0 : b1;
                        b0 = ps[t] ? key[t] : b0;
                    }
                    count += cnt;
                }
            }
        }
    }

    // final flush
    ins16(k, b0); ins16(k, b1); ins16(k, b2); ins16(k, b3);

    // k[0..15] sorted ascending by (dist, idx) = reference neighbor order
    #pragma unroll
    for (int kk = 0; kk < KK; ++kk) s_idx[warp][lane][kk] = (int)(u32)k[kk];
    __syncwarp();

    // ---- gather + write: warp iterates its 32 queries, lanes split channels ----
    for (int qq = 0; qq < 32; ++qq) {
        int n = q0b + warp * 32 + qq;
        float c0 = fb[(size_t)n * CC + lane];
        float c1 = fb[(size_t)n * CC + lane + 32];
        float* ob = out + (size_t)(b * NN + n) * KK * (2 * CC);
        #pragma unroll
        for (int kk = 0; kk < KK; ++kk) {
            int nbv = s_idx[warp][qq][kk];
            const float* fr = fb + (size_t)nbv * CC;
            float g0 = __ldg(fr + lane);
            float g1 = __ldg(fr + lane + 32);
            float* orow = ob + kk * (2 * CC);
            __stcs(orow + lane,      g0);
            __stcs(orow + 32 + lane, g1);
            __stcs(orow + 64 + lane, g0 - c0);
            __stcs(orow + 96 + lane, g1 - c1);
        }
    }
}

extern "C" void kernel_launch(void* const* d_in, const int* in_sizes, int n_in,
                              void* d_out, int out_size) {
    const float* points   = (const float*)d_in[0];
    const float* features = (const float*)d_in[1];
    float* out = (float*)d_out;
    (void)in_sizes; (void)n_in; (void)out_size;
    norms_kernel<<<(BB * NN + 255) / 256, 256>>>(points);
    knn_select_kernel<<<BB * (NN / THREADS), THREADS>>>(points, features, out);
}